// round 15
// baseline (speedup 1.0000x reference)
#include <cuda_runtime.h>
#include <cuda_fp16.h>
#include <math.h>
#include <stdint.h>

#define BB 32
#define NN 1024
#define FF 128
#define RPB 16              // rows per fused block (512 threads)
#define NBLK (NN / RPB)     // 64 partial slabs
#define GC 32
#define CK 32

// State: E = exp(y) in [1, e], uint16 fixed-point: 64MB
__device__ unsigned short g_Q[BB * NN * NN];
__device__ float g_colsum[BB * NN];
__device__ float g_part[NBLK * BB * NN];          // 8MB colsum partials
__device__ __half g_F[BB * NN * NN];              // 64MB final E (fp16, GEMM A)
__device__ __half g_B[BB * NN * FF];              // 8MB scaled feature (fp16, GEMM B)

// ---------------- fixed-point (magic-number, no cvt pipe) ----------------
#define EMAXR 1.7182837f
#define K1C (EMAXR / 65535.0f)
#define C1C (1.0f - 8388608.0f * K1C)
#define K2C (65535.0f / EMAXR)
#define C2C (8388608.0f - K2C)

__device__ __forceinline__ float decE(uint32_t u16) {
    return fmaf(__uint_as_float(0x4B000000u | u16), K1C, C1C);
}
__device__ __forceinline__ uint32_t enc2(float a, float b) {
    uint32_t ba = __float_as_uint(fmaf(a, K2C, C2C));
    uint32_t bb = __float_as_uint(fmaf(b, K2C, C2C));
    return (ba & 0xFFFFu) | (bb << 16);
}

// ---------------- PTX helpers ----------------
__device__ __forceinline__ uint32_t smem_u32(const void* p) {
    uint32_t a;
    asm("{ .reg .u64 t; cvta.to.shared.u64 t, %1; cvt.u32.u64 %0, t; }" : "=r"(a) : "l"(p));
    return a;
}
#define CP16(dst, src) asm volatile("cp.async.cg.shared.global [%0], [%1], 16;" :: "r"(dst), "l"(src))
#define CP_COMMIT()    asm volatile("cp.async.commit_group;" ::: "memory")
#define CP_WAIT1()     asm volatile("cp.async.wait_group 1;" ::: "memory")
#define CP_WAIT0()     asm volatile("cp.async.wait_group 0;" ::: "memory")

__device__ __forceinline__ void ldsm_x4(uint32_t* r, uint32_t addr) {
    asm volatile("ldmatrix.sync.aligned.m8n8.x4.shared.b16 {%0,%1,%2,%3}, [%4];"
                 : "=r"(r[0]), "=r"(r[1]), "=r"(r[2]), "=r"(r[3]) : "r"(addr));
}
__device__ __forceinline__ void ldsm_x4_t(uint32_t* r, uint32_t addr) {
    asm volatile("ldmatrix.sync.aligned.m8n8.x4.trans.shared.b16 {%0,%1,%2,%3}, [%4];"
                 : "=r"(r[0]), "=r"(r[1]), "=r"(r[2]), "=r"(r[3]) : "r"(addr));
}
__device__ __forceinline__ void mma_f16(float* d, const uint32_t* a, const uint32_t* b) {
    asm volatile("mma.sync.aligned.m16n8k16.row.col.f32.f16.f16.f32 "
                 "{%0,%1,%2,%3}, {%4,%5,%6,%7}, {%8,%9}, {%0,%1,%2,%3};"
                 : "+f"(d[0]), "+f"(d[1]), "+f"(d[2]), "+f"(d[3])
                 : "r"(a[0]), "r"(a[1]), "r"(a[2]), "r"(a[3]), "r"(b[0]), "r"(b[1]));
}

union PackH4 { __half h[4]; uint2 u; };

// ===========================================================================
// Init: row softmax #1; 512 threads, 16 rows (2 row-groups of 8).
// ===========================================================================
__global__ __launch_bounds__(512, 2) void k_init(const float* __restrict__ tmpl,
                                                 const float* __restrict__ uni) {
    const int b = blockIdx.y, t = threadIdx.x;
    const int rh = t >> 8, tc = t & 255, j0 = tc * 4;
    const int rbase = blockIdx.x * RPB + rh * 8;
    __shared__ float part[16][256];
    __shared__ float rred[16];

    float4 x4[8];
#pragma unroll
    for (int rr = 0; rr < 8; rr++) {
        const int row = rbase + rr;
        float4 u = *(const float4*)&uni[((size_t)b * NN + row) * NN + j0];
        float4 tm = *(const float4*)&tmpl[(size_t)row * NN + j0];
        float4 x;
        x.x = (tm.x - __logf(-logf(u.x + 1e-12f) + 1e-12f)) * 5.0f;
        x.y = (tm.y - __logf(-logf(u.y + 1e-12f) + 1e-12f)) * 5.0f;
        x.z = (tm.z - __logf(-logf(u.z + 1e-12f) + 1e-12f)) * 5.0f;
        x.w = (tm.w - __logf(-logf(u.w + 1e-12f) + 1e-12f)) * 5.0f;
        x4[rr] = x;
        part[rh * 8 + rr][tc] = fmaxf(fmaxf(x.x, x.y), fmaxf(x.z, x.w));
    }
    __syncthreads();
    {
        const int w = t >> 5, lane = t & 31;   // 16 warps -> 16 rows
        float v = part[w][lane];
#pragma unroll
        for (int k = 1; k < 8; k++) v = fmaxf(v, part[w][lane + k * 32]);
#pragma unroll
        for (int o = 16; o > 0; o >>= 1) v = fmaxf(v, __shfl_xor_sync(0xffffffffu, v, o));
        if (lane == 0) rred[w] = v;
    }
    __syncthreads();
#pragma unroll
    for (int rr = 0; rr < 8; rr++) {
        const float mx = rred[rh * 8 + rr];
        float4 e;
        e.x = __expf(x4[rr].x - mx);
        e.y = __expf(x4[rr].y - mx);
        e.z = __expf(x4[rr].z - mx);
        e.w = __expf(x4[rr].w - mx);
        x4[rr] = e;
        part[rh * 8 + rr][tc] = (e.x + e.y) + (e.z + e.w);
    }
    __syncthreads();
    {
        const int w = t >> 5, lane = t & 31;
        float v = part[w][lane];
#pragma unroll
        for (int k = 1; k < 8; k++) v += part[w][lane + k * 32];
#pragma unroll
        for (int o = 16; o > 0; o >>= 1) v += __shfl_xor_sync(0xffffffffu, v, o);
        if (lane == 0) rred[w] = 1.0f / v;
    }
    __syncthreads();
    float4 cs = make_float4(0.f, 0.f, 0.f, 0.f);
#pragma unroll
    for (int rr = 0; rr < 8; rr++) {
        const float inv = rred[rh * 8 + rr];
        float Ex = __expf(x4[rr].x * inv);
        float Ey = __expf(x4[rr].y * inv);
        float Ez = __expf(x4[rr].z * inv);
        float Ew = __expf(x4[rr].w * inv);
        uint2 o;
        o.x = enc2(Ex, Ey);
        o.y = enc2(Ez, Ew);
        *(uint2*)&g_Q[((size_t)b * NN + rbase + rr) * NN + j0] = o;
        cs.x += Ex; cs.y += Ey; cs.z += Ez; cs.w += Ew;
    }
    float4* csp = (float4*)part;
    csp[rh * 256 + tc] = cs;
    __syncthreads();
    if (t < 256) {
        float4 a = csp[t], q = csp[256 + t];
        a.x += q.x; a.y += q.y; a.z += q.z; a.w += q.w;
        *(float4*)&g_part[((size_t)blockIdx.x * BB + b) * NN + t * 4] = a;
    }
}

// ===========================================================================
// Reduce 64 partial slabs -> colsum. grid (8, BB), 128 cols/block, MLP 8.
// ===========================================================================
__global__ __launch_bounds__(256) void k_reduce() {
    const int b = blockIdx.y, g = blockIdx.x, t = threadIdx.x;
    const int c = t & 31, p0 = t >> 5;
    const float4* P = (const float4*)g_part;
    float4 s = make_float4(0.f, 0.f, 0.f, 0.f);
#pragma unroll
    for (int p = p0; p < NBLK; p += 8) {
        float4 v = P[((size_t)p * BB + b) * 256 + g * 32 + c];
        s.x += v.x; s.y += v.y; s.z += v.z; s.w += v.w;
    }
    __shared__ float4 sm[8][32];
    sm[p0][c] = s;
    __syncthreads();
    if (t < 32) {
        float4 a = sm[0][t];
#pragma unroll
        for (int p = 1; p < 8; p++) {
            float4 v = sm[p][t];
            a.x += v.x; a.y += v.y; a.z += v.z; a.w += v.w;
        }
        *(float4*)&g_colsum[b * NN + g * 128 + t * 4] = a;
    }
}

// ===========================================================================
// Fused pair (col+row softmax) on u16 state; 512 threads, 16 rows.
// ===========================================================================
__global__ __launch_bounds__(512, 2) void k_fused() {
    const int b = blockIdx.y, t = threadIdx.x;
    const int rh = t >> 8, tc = t & 255, j0 = tc * 4;
    const int rbase = blockIdx.x * RPB + rh * 8;
    __shared__ float part[16][256];
    __shared__ float rinv[16];

    float4 cv = *(const float4*)&g_colsum[b * NN + j0];
    const float4 ic = make_float4(1.0f / cv.x, 1.0f / cv.y, 1.0f / cv.z, 1.0f / cv.w);

    float4 r4[8];
#pragma unroll
    for (int rr = 0; rr < 8; rr++) {
        uint2 w = *(const uint2*)&g_Q[((size_t)b * NN + rbase + rr) * NN + j0];
        float4 r;
        r.x = __expf(decE(w.x & 0xFFFFu) * ic.x);
        r.y = __expf(decE(w.x >> 16) * ic.y);
        r.z = __expf(decE(w.y & 0xFFFFu) * ic.z);
        r.w = __expf(decE(w.y >> 16) * ic.w);
        r4[rr] = r;
        part[rh * 8 + rr][tc] = (r.x + r.y) + (r.z + r.w);
    }
    __syncthreads();
    {
        const int w = t >> 5, lane = t & 31;
        float v = part[w][lane];
#pragma unroll
        for (int k = 1; k < 8; k++) v += part[w][lane + k * 32];
#pragma unroll
        for (int o = 16; o > 0; o >>= 1) v += __shfl_xor_sync(0xffffffffu, v, o);
        if (lane == 0) rinv[w] = 1.0f / v;
    }
    __syncthreads();
    float4 cs = make_float4(0.f, 0.f, 0.f, 0.f);
#pragma unroll
    for (int rr = 0; rr < 8; rr++) {
        const float ir = rinv[rh * 8 + rr];
        float Ex = __expf(r4[rr].x * ir);
        float Ey = __expf(r4[rr].y * ir);
        float Ez = __expf(r4[rr].z * ir);
        float Ew = __expf(r4[rr].w * ir);
        uint2 o;
        o.x = enc2(Ex, Ey);
        o.y = enc2(Ez, Ew);
        *(uint2*)&g_Q[((size_t)b * NN + rbase + rr) * NN + j0] = o;
        cs.x += Ex; cs.y += Ey; cs.z += Ez; cs.w += Ew;
    }
    float4* csp = (float4*)part;
    csp[rh * 256 + tc] = cs;
    __syncthreads();
    if (t < 256) {
        float4 a = csp[t], q = csp[256 + t];
        a.x += q.x; a.y += q.y; a.z += q.z; a.w += q.w;
        *(float4*)&g_part[((size_t)blockIdx.x * BB + b) * NN + t * 4] = a;
    }
}

// Last pair: col#9 + row#10; store E10 as fp16 + partials. 512 threads.
__global__ __launch_bounds__(512, 2) void k_fused_last() {
    const int b = blockIdx.y, t = threadIdx.x;
    const int rh = t >> 8, tc = t & 255, j0 = tc * 4;
    const int rbase = blockIdx.x * RPB + rh * 8;
    __shared__ float part[16][256];
    __shared__ float rinv[16];

    float4 cv = *(const float4*)&g_colsum[b * NN + j0];
    const float4 ic = make_float4(1.0f / cv.x, 1.0f / cv.y, 1.0f / cv.z, 1.0f / cv.w);

    float4 r4[8];
#pragma unroll
    for (int rr = 0; rr < 8; rr++) {
        uint2 w = *(const uint2*)&g_Q[((size_t)b * NN + rbase + rr) * NN + j0];
        float4 r;
        r.x = __expf(decE(w.x & 0xFFFFu) * ic.x);
        r.y = __expf(decE(w.x >> 16) * ic.y);
        r.z = __expf(decE(w.y & 0xFFFFu) * ic.z);
        r.w = __expf(decE(w.y >> 16) * ic.w);
        r4[rr] = r;
        part[rh * 8 + rr][tc] = (r.x + r.y) + (r.z + r.w);
    }
    __syncthreads();
    {
        const int w = t >> 5, lane = t & 31;
        float v = part[w][lane];
#pragma unroll
        for (int k = 1; k < 8; k++) v += part[w][lane + k * 32];
#pragma unroll
        for (int o = 16; o > 0; o >>= 1) v += __shfl_xor_sync(0xffffffffu, v, o);
        if (lane == 0) rinv[w] = 1.0f / v;
    }
    __syncthreads();
    float4 cs = make_float4(0.f, 0.f, 0.f, 0.f);
#pragma unroll
    for (int rr = 0; rr < 8; rr++) {
        const float ir = rinv[rh * 8 + rr];
        float Ex = __expf(r4[rr].x * ir);
        float Ey = __expf(r4[rr].y * ir);
        float Ez = __expf(r4[rr].z * ir);
        float Ew = __expf(r4[rr].w * ir);
        PackH4 H;
        H.h[0] = __float2half_rn(Ex);
        H.h[1] = __float2half_rn(Ey);
        H.h[2] = __float2half_rn(Ez);
        H.h[3] = __float2half_rn(Ew);
        *(uint2*)&g_F[((size_t)b * NN + rbase + rr) * NN + j0] = H.u;
        cs.x += Ex; cs.y += Ey; cs.z += Ez; cs.w += Ew;
    }
    float4* csp = (float4*)part;
    csp[rh * 256 + tc] = cs;
    __syncthreads();
    if (t < 256) {
        float4 a = csp[t], q = csp[256 + t];
        a.x += q.x; a.y += q.y; a.z += q.z; a.w += q.w;
        *(float4*)&g_part[((size_t)blockIdx.x * BB + b) * NN + t * 4] = a;
    }
}

// ===========================================================================
// prepB: integrated final colsum reduce (64 slabs); B = fp16(1024*ic*feat)
// grid (128, BB), 256 thr, 8 k-rows per block.
// ===========================================================================
__global__ __launch_bounds__(256) void k_prepB(const float* __restrict__ feat) {
    const int b = blockIdx.y, k0 = blockIdx.x * 8, t = threadIdx.x;
    __shared__ float sm[32][8];
    __shared__ float ics[8];
    {
        const int kk = t & 7, p0 = t >> 3;          // 32 p-groups over 64 slabs
        float s = 0.f;
#pragma unroll
        for (int p = p0; p < NBLK; p += 32)
            s += g_part[((size_t)p * BB + b) * NN + k0 + kk];
        sm[p0][kk] = s;
        __syncthreads();
        if (t < 8) {
            float a = 0.f;
#pragma unroll
            for (int p = 0; p < 32; p++) a += sm[p][t];
            ics[t] = 1024.0f / a;
        }
        __syncthreads();
    }
    const int k = k0 + (t >> 5);
    const int f4 = (t & 31) * 4;
    const float ic = ics[t >> 5];
    float4 v = *(const float4*)&feat[((size_t)b * NN + k) * FF + f4];
    PackH4 H;
    H.h[0] = __float2half_rn(v.x * ic);
    H.h[1] = __float2half_rn(v.y * ic);
    H.h[2] = __float2half_rn(v.z * ic);
    H.h[3] = __float2half_rn(v.w * ic);
    *(uint2*)&g_B[((size_t)b * NN + k) * FF + f4] = H.u;
}

// ===========================================================================
// fp16 single-product HMMA GEMM: out = 2^-10 * F @ B  (R14 passing version)
// ===========================================================================
#define SBUF 18944
#define BOFF 10240

__global__ __launch_bounds__(256, 2) void k_gemm(float* __restrict__ out) {
    extern __shared__ char smem[];
    const int b = blockIdx.y, i0 = blockIdx.x * 128, t = threadIdx.x;
    const int wid = t >> 5, lane = t & 31;
    const int wm = wid & 3, wn = wid >> 2;
    const uint32_t sb = smem_u32(smem);

    const int rowA = t >> 1, halfA = (t & 1) * 32;
    const int rowB = t >> 3, pB = (t & 7) * 32;
    const char* srcA = (const char*)(g_F + ((size_t)b * NN + i0 + rowA) * NN) + halfA;
    const char* srcB = (const char*)(g_B + (size_t)b * NN * FF) + rowB * 256 + pB;
    const uint32_t dA = sb + rowA * 80 + halfA;
    const uint32_t dB = sb + BOFF + rowB * 272 + pB;

#define ISSUE_CHUNK(cc)  do {                                            \
        const int _s = (cc) & 1;                                         \
        const size_t _ao = (size_t)(cc) * CK * 2;                        \
        CP16(dA + _s * SBUF,      srcA + _ao);                           \
        CP16(dA + _s * SBUF + 16, srcA + _ao + 16);                      \
        const size_t _bo = (size_t)(cc) * CK * 256;                      \
        CP16(dB + _s * SBUF,      srcB + _bo);                           \
        CP16(dB + _s * SBUF + 16, srcB + _bo + 16);                      \
        CP_COMMIT();                                                     \
    } while (0)

    float acc[2][8][4];
#pragma unroll
    for (int mf = 0; mf < 2; mf++)
#pragma unroll
        for (int nf = 0; nf < 8; nf++)
#pragma unroll
            for (int q = 0; q < 4; q++) acc[mf][nf][q] = 0.f;

    ISSUE_CHUNK(0);

    for (int c = 0; c < GC; ++c) {
        if (c < GC - 1) { ISSUE_CHUNK(c + 1); CP_WAIT1(); }
        else            { CP_WAIT0(); }
        __syncthreads();

        const uint32_t buf = sb + (c & 1) * SBUF;
#pragma unroll
        for (int ks = 0; ks < 2; ks++) {
            uint32_t aF[2][4];
#pragma unroll
            for (int mf = 0; mf < 2; mf++) {
                const int r0 = wm * 32 + mf * 16;
                ldsm_x4(aF[mf], buf + (r0 + (lane & 15)) * 80 + ks * 32 + (lane >> 4) * 16);
            }
            uint32_t bF[4][4];
#pragma unroll
            for (int ng = 0; ng < 4; ng++) {
                const int n0 = wn * 64 + ng * 16;
                ldsm_x4_t(bF[ng], buf + BOFF + (ks * 16 + (lane & 15)) * 272 + n0 * 2 + (lane >> 4) * 16);
            }
#pragma unroll
            for (int mf = 0; mf < 2; mf++)
#pragma unroll
                for (int ng = 0; ng < 4; ng++)
#pragma unroll
                    for (int h = 0; h < 2; h++)
                        mma_f16(acc[mf][ng * 2 + h], aF[mf], &bF[ng][h * 2]);
        }
        __syncthreads();
    }

    const int gid = lane >> 2, t4 = lane & 3;
    const float sc = 0.0009765625f;   // 2^-10
#pragma unroll
    for (int mf = 0; mf < 2; mf++) {
        const int row = i0 + wm * 32 + mf * 16 + gid;
#pragma unroll
        for (int nf = 0; nf < 8; nf++) {
            const int col = wn * 64 + nf * 8 + t4 * 2;
            const float* d = acc[mf][nf];
            *(float2*)&out[((size_t)b * NN + row) * FF + col]     = make_float2(d[0] * sc, d[1] * sc);
            *(float2*)&out[((size_t)b * NN + row + 8) * FF + col] = make_float2(d[2] * sc, d[3] * sc);
        }
    }
}

// ===========================================================================
extern "C" void kernel_launch(void* const* d_in, const int* in_sizes, int n_in,
                              void* d_out, int out_size) {
    const float* feat = (const float*)d_in[0];   // [B,N,F]
    const float* tmpl = (const float*)d_in[1];   // [1,N,N]
    const float* uni  = (const float*)d_in[2];   // [B,N,N]
    float* out = (float*)d_out;                  // [B,N,F]

    cudaFuncSetAttribute(k_gemm, cudaFuncAttributeMaxDynamicSharedMemorySize, 2 * SBUF);

    k_init<<<dim3(NBLK, BB), 512>>>(tmpl, uni);
    k_reduce<<<dim3(8, BB), 256>>>();
    for (int it = 0; it < 8; ++it) {
        k_fused<<<dim3(NBLK, BB), 512>>>();
        k_reduce<<<dim3(8, BB), 256>>>();
    }
    k_fused_last<<<dim3(NBLK, BB), 512>>>();
    k_prepB<<<dim3(NN / 8, BB), 256>>>(feat);
    k_gemm<<<dim3(8, BB), 256, 2 * SBUF>>>(out);
}

// round 16
// speedup vs baseline: 1.0142x; 1.0142x over previous
#include <cuda_runtime.h>
#include <cuda_fp16.h>
#include <math.h>
#include <stdint.h>

#define BB 32
#define NN 1024
#define FF 128
#define RPB 16              // rows per fused block (512 threads)
#define NBLK (NN / RPB)     // 64 partial slabs
#define GC 32
#define CK 32

// State: E = exp(y) in [1, e], uint16 fixed-point: 64MB
__device__ unsigned short g_Q[BB * NN * NN];
__device__ float g_colsum[BB * NN];
__device__ float g_part[NBLK * BB * NN];          // 8MB colsum partials
__device__ __half g_F[BB * NN * NN];              // 64MB final E (fp16, GEMM A)
__device__ __half g_B[BB * NN * FF];              // 8MB scaled feature (fp16, GEMM B)

// ---------------- fixed-point (magic-number, no cvt pipe) ----------------
#define EMAXR 1.7182837f
#define K1C (EMAXR / 65535.0f)
#define C1C (1.0f - 8388608.0f * K1C)
#define K2C (65535.0f / EMAXR)
#define C2C (8388608.0f - K2C)

__device__ __forceinline__ float decE(uint32_t u16) {
    return fmaf(__uint_as_float(0x4B000000u | u16), K1C, C1C);
}
__device__ __forceinline__ uint32_t enc2(float a, float b) {
    uint32_t ba = __float_as_uint(fmaf(a, K2C, C2C));
    uint32_t bb = __float_as_uint(fmaf(b, K2C, C2C));
    return (ba & 0xFFFFu) | (bb << 16);
}

// ---------------- PTX helpers ----------------
__device__ __forceinline__ uint32_t smem_u32(const void* p) {
    uint32_t a;
    asm("{ .reg .u64 t; cvta.to.shared.u64 t, %1; cvt.u32.u64 %0, t; }" : "=r"(a) : "l"(p));
    return a;
}
#define CP16(dst, src) asm volatile("cp.async.cg.shared.global [%0], [%1], 16;" :: "r"(dst), "l"(src))
#define CP_COMMIT()    asm volatile("cp.async.commit_group;" ::: "memory")
#define CP_WAIT2()     asm volatile("cp.async.wait_group 2;" ::: "memory")
#define CP_WAIT1()     asm volatile("cp.async.wait_group 1;" ::: "memory")
#define CP_WAIT0()     asm volatile("cp.async.wait_group 0;" ::: "memory")

__device__ __forceinline__ void ldsm_x4(uint32_t* r, uint32_t addr) {
    asm volatile("ldmatrix.sync.aligned.m8n8.x4.shared.b16 {%0,%1,%2,%3}, [%4];"
                 : "=r"(r[0]), "=r"(r[1]), "=r"(r[2]), "=r"(r[3]) : "r"(addr));
}
__device__ __forceinline__ void ldsm_x4_t(uint32_t* r, uint32_t addr) {
    asm volatile("ldmatrix.sync.aligned.m8n8.x4.trans.shared.b16 {%0,%1,%2,%3}, [%4];"
                 : "=r"(r[0]), "=r"(r[1]), "=r"(r[2]), "=r"(r[3]) : "r"(addr));
}
__device__ __forceinline__ void mma_f16(float* d, const uint32_t* a, const uint32_t* b) {
    asm volatile("mma.sync.aligned.m16n8k16.row.col.f32.f16.f16.f32 "
                 "{%0,%1,%2,%3}, {%4,%5,%6,%7}, {%8,%9}, {%0,%1,%2,%3};"
                 : "+f"(d[0]), "+f"(d[1]), "+f"(d[2]), "+f"(d[3])
                 : "r"(a[0]), "r"(a[1]), "r"(a[2]), "r"(a[3]), "r"(b[0]), "r"(b[1]));
}

union PackH4 { __half h[4]; uint2 u; };

// ===========================================================================
// Init: row softmax #1; 512 threads, 16 rows (2 row-groups of 8).
// ===========================================================================
__global__ __launch_bounds__(512, 2) void k_init(const float* __restrict__ tmpl,
                                                 const float* __restrict__ uni) {
    const int b = blockIdx.y, t = threadIdx.x;
    const int rh = t >> 8, tc = t & 255, j0 = tc * 4;
    const int rbase = blockIdx.x * RPB + rh * 8;
    __shared__ float part[16][256];
    __shared__ float rred[16];

    float4 x4[8];
#pragma unroll
    for (int rr = 0; rr < 8; rr++) {
        const int row = rbase + rr;
        float4 u = *(const float4*)&uni[((size_t)b * NN + row) * NN + j0];
        float4 tm = *(const float4*)&tmpl[(size_t)row * NN + j0];
        float4 x;
        x.x = (tm.x - __logf(-logf(u.x + 1e-12f) + 1e-12f)) * 5.0f;
        x.y = (tm.y - __logf(-logf(u.y + 1e-12f) + 1e-12f)) * 5.0f;
        x.z = (tm.z - __logf(-logf(u.z + 1e-12f) + 1e-12f)) * 5.0f;
        x.w = (tm.w - __logf(-logf(u.w + 1e-12f) + 1e-12f)) * 5.0f;
        x4[rr] = x;
        part[rh * 8 + rr][tc] = fmaxf(fmaxf(x.x, x.y), fmaxf(x.z, x.w));
    }
    __syncthreads();
    {
        const int w = t >> 5, lane = t & 31;   // 16 warps -> 16 rows
        float v = part[w][lane];
#pragma unroll
        for (int k = 1; k < 8; k++) v = fmaxf(v, part[w][lane + k * 32]);
#pragma unroll
        for (int o = 16; o > 0; o >>= 1) v = fmaxf(v, __shfl_xor_sync(0xffffffffu, v, o));
        if (lane == 0) rred[w] = v;
    }
    __syncthreads();
#pragma unroll
    for (int rr = 0; rr < 8; rr++) {
        const float mx = rred[rh * 8 + rr];
        float4 e;
        e.x = __expf(x4[rr].x - mx);
        e.y = __expf(x4[rr].y - mx);
        e.z = __expf(x4[rr].z - mx);
        e.w = __expf(x4[rr].w - mx);
        x4[rr] = e;
        part[rh * 8 + rr][tc] = (e.x + e.y) + (e.z + e.w);
    }
    __syncthreads();
    {
        const int w = t >> 5, lane = t & 31;
        float v = part[w][lane];
#pragma unroll
        for (int k = 1; k < 8; k++) v += part[w][lane + k * 32];
#pragma unroll
        for (int o = 16; o > 0; o >>= 1) v += __shfl_xor_sync(0xffffffffu, v, o);
        if (lane == 0) rred[w] = 1.0f / v;
    }
    __syncthreads();
    float4 cs = make_float4(0.f, 0.f, 0.f, 0.f);
#pragma unroll
    for (int rr = 0; rr < 8; rr++) {
        const float inv = rred[rh * 8 + rr];
        float Ex = __expf(x4[rr].x * inv);
        float Ey = __expf(x4[rr].y * inv);
        float Ez = __expf(x4[rr].z * inv);
        float Ew = __expf(x4[rr].w * inv);
        uint2 o;
        o.x = enc2(Ex, Ey);
        o.y = enc2(Ez, Ew);
        *(uint2*)&g_Q[((size_t)b * NN + rbase + rr) * NN + j0] = o;
        cs.x += Ex; cs.y += Ey; cs.z += Ez; cs.w += Ew;
    }
    float4* csp = (float4*)part;
    csp[rh * 256 + tc] = cs;
    __syncthreads();
    if (t < 256) {
        float4 a = csp[t], q = csp[256 + t];
        a.x += q.x; a.y += q.y; a.z += q.z; a.w += q.w;
        *(float4*)&g_part[((size_t)blockIdx.x * BB + b) * NN + t * 4] = a;
    }
}

// ===========================================================================
// Reduce 64 slabs -> colsum. grid (32, BB) = 1024 blocks, 32 cols each, MLP 2.
// ===========================================================================
__global__ __launch_bounds__(256) void k_reduce() {
    const int b = blockIdx.y, g = blockIdx.x, t = threadIdx.x;
    const int c = t & 7, p0 = t >> 3;            // 32 slab-groups x 8 float4 cols
    const float4* P = (const float4*)g_part;
    float4 s = make_float4(0.f, 0.f, 0.f, 0.f);
#pragma unroll
    for (int p = p0; p < NBLK; p += 32) {        // 2 loads per thread
        float4 v = P[((size_t)p * BB + b) * 256 + g * 8 + c];
        s.x += v.x; s.y += v.y; s.z += v.z; s.w += v.w;
    }
    __shared__ float4 sm[32][8];
    sm[p0][c] = s;
    __syncthreads();
    if (t < 8) {
        float4 a = sm[0][t];
#pragma unroll
        for (int p = 1; p < 32; p++) {
            float4 v = sm[p][t];
            a.x += v.x; a.y += v.y; a.z += v.z; a.w += v.w;
        }
        *(float4*)&g_colsum[b * NN + g * 32 + t * 4] = a;
    }
}

// ===========================================================================
// Fused pair (col+row softmax) on u16 state; 512 threads, 16 rows.
// ===========================================================================
__global__ __launch_bounds__(512, 2) void k_fused() {
    const int b = blockIdx.y, t = threadIdx.x;
    const int rh = t >> 8, tc = t & 255, j0 = tc * 4;
    const int rbase = blockIdx.x * RPB + rh * 8;
    __shared__ float part[16][256];
    __shared__ float rinv[16];

    float4 cv = *(const float4*)&g_colsum[b * NN + j0];
    const float4 ic = make_float4(1.0f / cv.x, 1.0f / cv.y, 1.0f / cv.z, 1.0f / cv.w);

    float4 r4[8];
#pragma unroll
    for (int rr = 0; rr < 8; rr++) {
        uint2 w = *(const uint2*)&g_Q[((size_t)b * NN + rbase + rr) * NN + j0];
        float4 r;
        r.x = __expf(decE(w.x & 0xFFFFu) * ic.x);
        r.y = __expf(decE(w.x >> 16) * ic.y);
        r.z = __expf(decE(w.y & 0xFFFFu) * ic.z);
        r.w = __expf(decE(w.y >> 16) * ic.w);
        r4[rr] = r;
        part[rh * 8 + rr][tc] = (r.x + r.y) + (r.z + r.w);
    }
    __syncthreads();
    {
        const int w = t >> 5, lane = t & 31;
        float v = part[w][lane];
#pragma unroll
        for (int k = 1; k < 8; k++) v += part[w][lane + k * 32];
#pragma unroll
        for (int o = 16; o > 0; o >>= 1) v += __shfl_xor_sync(0xffffffffu, v, o);
        if (lane == 0) rinv[w] = 1.0f / v;
    }
    __syncthreads();
    float4 cs = make_float4(0.f, 0.f, 0.f, 0.f);
#pragma unroll
    for (int rr = 0; rr < 8; rr++) {
        const float ir = rinv[rh * 8 + rr];
        float Ex = __expf(r4[rr].x * ir);
        float Ey = __expf(r4[rr].y * ir);
        float Ez = __expf(r4[rr].z * ir);
        float Ew = __expf(r4[rr].w * ir);
        uint2 o;
        o.x = enc2(Ex, Ey);
        o.y = enc2(Ez, Ew);
        *(uint2*)&g_Q[((size_t)b * NN + rbase + rr) * NN + j0] = o;
        cs.x += Ex; cs.y += Ey; cs.z += Ez; cs.w += Ew;
    }
    float4* csp = (float4*)part;
    csp[rh * 256 + tc] = cs;
    __syncthreads();
    if (t < 256) {
        float4 a = csp[t], q = csp[256 + t];
        a.x += q.x; a.y += q.y; a.z += q.z; a.w += q.w;
        *(float4*)&g_part[((size_t)blockIdx.x * BB + b) * NN + t * 4] = a;
    }
}

// Last pair: col#9 + row#10; store E10 as fp16 + partials. 512 threads.
__global__ __launch_bounds__(512, 2) void k_fused_last() {
    const int b = blockIdx.y, t = threadIdx.x;
    const int rh = t >> 8, tc = t & 255, j0 = tc * 4;
    const int rbase = blockIdx.x * RPB + rh * 8;
    __shared__ float part[16][256];
    __shared__ float rinv[16];

    float4 cv = *(const float4*)&g_colsum[b * NN + j0];
    const float4 ic = make_float4(1.0f / cv.x, 1.0f / cv.y, 1.0f / cv.z, 1.0f / cv.w);

    float4 r4[8];
#pragma unroll
    for (int rr = 0; rr < 8; rr++) {
        uint2 w = *(const uint2*)&g_Q[((size_t)b * NN + rbase + rr) * NN + j0];
        float4 r;
        r.x = __expf(decE(w.x & 0xFFFFu) * ic.x);
        r.y = __expf(decE(w.x >> 16) * ic.y);
        r.z = __expf(decE(w.y & 0xFFFFu) * ic.z);
        r.w = __expf(decE(w.y >> 16) * ic.w);
        r4[rr] = r;
        part[rh * 8 + rr][tc] = (r.x + r.y) + (r.z + r.w);
    }
    __syncthreads();
    {
        const int w = t >> 5, lane = t & 31;
        float v = part[w][lane];
#pragma unroll
        for (int k = 1; k < 8; k++) v += part[w][lane + k * 32];
#pragma unroll
        for (int o = 16; o > 0; o >>= 1) v += __shfl_xor_sync(0xffffffffu, v, o);
        if (lane == 0) rinv[w] = 1.0f / v;
    }
    __syncthreads();
    float4 cs = make_float4(0.f, 0.f, 0.f, 0.f);
#pragma unroll
    for (int rr = 0; rr < 8; rr++) {
        const float ir = rinv[rh * 8 + rr];
        float Ex = __expf(r4[rr].x * ir);
        float Ey = __expf(r4[rr].y * ir);
        float Ez = __expf(r4[rr].z * ir);
        float Ew = __expf(r4[rr].w * ir);
        PackH4 H;
        H.h[0] = __float2half_rn(Ex);
        H.h[1] = __float2half_rn(Ey);
        H.h[2] = __float2half_rn(Ez);
        H.h[3] = __float2half_rn(Ew);
        *(uint2*)&g_F[((size_t)b * NN + rbase + rr) * NN + j0] = H.u;
        cs.x += Ex; cs.y += Ey; cs.z += Ez; cs.w += Ew;
    }
    float4* csp = (float4*)part;
    csp[rh * 256 + tc] = cs;
    __syncthreads();
    if (t < 256) {
        float4 a = csp[t], q = csp[256 + t];
        a.x += q.x; a.y += q.y; a.z += q.z; a.w += q.w;
        *(float4*)&g_part[((size_t)blockIdx.x * BB + b) * NN + t * 4] = a;
    }
}

// ===========================================================================
// prepB: integrated final colsum reduce (64 slabs); B = fp16(1024*ic*feat)
// grid (128, BB), 256 thr, 8 k-rows per block.
// ===========================================================================
__global__ __launch_bounds__(256) void k_prepB(const float* __restrict__ feat) {
    const int b = blockIdx.y, k0 = blockIdx.x * 8, t = threadIdx.x;
    __shared__ float sm[32][8];
    __shared__ float ics[8];
    {
        const int kk = t & 7, p0 = t >> 3;          // 32 p-groups over 64 slabs
        float s = 0.f;
#pragma unroll
        for (int p = p0; p < NBLK; p += 32)
            s += g_part[((size_t)p * BB + b) * NN + k0 + kk];
        sm[p0][kk] = s;
        __syncthreads();
        if (t < 8) {
            float a = 0.f;
#pragma unroll
            for (int p = 0; p < 32; p++) a += sm[p][t];
            ics[t] = 1024.0f / a;
        }
        __syncthreads();
    }
    const int k = k0 + (t >> 5);
    const int f4 = (t & 31) * 4;
    const float ic = ics[t >> 5];
    float4 v = *(const float4*)&feat[((size_t)b * NN + k) * FF + f4];
    PackH4 H;
    H.h[0] = __float2half_rn(v.x * ic);
    H.h[1] = __float2half_rn(v.y * ic);
    H.h[2] = __float2half_rn(v.z * ic);
    H.h[3] = __float2half_rn(v.w * ic);
    *(uint2*)&g_B[((size_t)b * NN + k) * FF + f4] = H.u;
}

// ===========================================================================
// fp16 single-product HMMA GEMM: out = 2^-10 * F @ B
// 4-stage cp.async ring (3 chunks in flight) to hide DRAM latency.
// ===========================================================================
#define SBUF 18944
#define BOFF 10240
#define NSTAGE 4

__global__ __launch_bounds__(256, 2) void k_gemm(float* __restrict__ out) {
    extern __shared__ char smem[];
    const int b = blockIdx.y, i0 = blockIdx.x * 128, t = threadIdx.x;
    const int wid = t >> 5, lane = t & 31;
    const int wm = wid & 3, wn = wid >> 2;
    const uint32_t sb = smem_u32(smem);

    const int rowA = t >> 1, halfA = (t & 1) * 32;
    const int rowB = t >> 3, pB = (t & 7) * 32;
    const char* srcA = (const char*)(g_F + ((size_t)b * NN + i0 + rowA) * NN) + halfA;
    const char* srcB = (const char*)(g_B + (size_t)b * NN * FF) + rowB * 256 + pB;
    const uint32_t dA = sb + rowA * 80 + halfA;
    const uint32_t dB = sb + BOFF + rowB * 272 + pB;

#define ISSUE_CHUNK(cc)  do {                                            \
        const int _s = (cc) & (NSTAGE - 1);                              \
        const size_t _ao = (size_t)(cc) * CK * 2;                        \
        CP16(dA + _s * SBUF,      srcA + _ao);                           \
        CP16(dA + _s * SBUF + 16, srcA + _ao + 16);                      \
        const size_t _bo = (size_t)(cc) * CK * 256;                      \
        CP16(dB + _s * SBUF,      srcB + _bo);                           \
        CP16(dB + _s * SBUF + 16, srcB + _bo + 16);                      \
        CP_COMMIT();                                                     \
    } while (0)

    float acc[2][8][4];
#pragma unroll
    for (int mf = 0; mf < 2; mf++)
#pragma unroll
        for (int nf = 0; nf < 8; nf++)
#pragma unroll
            for (int q = 0; q < 4; q++) acc[mf][nf][q] = 0.f;

    ISSUE_CHUNK(0);
    ISSUE_CHUNK(1);
    ISSUE_CHUNK(2);

    for (int c = 0; c < GC; ++c) {
        if (c < GC - 2)       CP_WAIT2();   // 3 pending -> oldest (c) done
        else if (c == GC - 2) CP_WAIT1();
        else                  CP_WAIT0();
        __syncthreads();

        const uint32_t buf = sb + (c & (NSTAGE - 1)) * SBUF;
#pragma unroll
        for (int ks = 0; ks < 2; ks++) {
            uint32_t aF[2][4];
#pragma unroll
            for (int mf = 0; mf < 2; mf++) {
                const int r0 = wm * 32 + mf * 16;
                ldsm_x4(aF[mf], buf + (r0 + (lane & 15)) * 80 + ks * 32 + (lane >> 4) * 16);
            }
            uint32_t bF[4][4];
#pragma unroll
            for (int ng = 0; ng < 4; ng++) {
                const int n0 = wn * 64 + ng * 16;
                ldsm_x4_t(bF[ng], buf + BOFF + (ks * 16 + (lane & 15)) * 272 + n0 * 2 + (lane >> 4) * 16);
            }
#pragma unroll
            for (int mf = 0; mf < 2; mf++)
#pragma unroll
                for (int ng = 0; ng < 4; ng++)
#pragma unroll
                    for (int h = 0; h < 2; h++)
                        mma_f16(acc[mf][ng * 2 + h], aF[mf], &bF[ng][h * 2]);
        }
        if (c + 3 < GC) ISSUE_CHUNK(c + 3);
    }

    const int gid = lane >> 2, t4 = lane & 3;
    const float sc = 0.0009765625f;   // 2^-10
#pragma unroll
    for (int mf = 0; mf < 2; mf++) {
        const int row = i0 + wm * 32 + mf * 16 + gid;
#pragma unroll
        for (int nf = 0; nf < 8; nf++) {
            const int col = wn * 64 + nf * 8 + t4 * 2;
            const float* d = acc[mf][nf];
            *(float2*)&out[((size_t)b * NN + row) * FF + col]     = make_float2(d[0] * sc, d[1] * sc);
            *(float2*)&out[((size_t)b * NN + row + 8) * FF + col] = make_float2(d[2] * sc, d[3] * sc);
        }
    }
}

// ===========================================================================
extern "C" void kernel_launch(void* const* d_in, const int* in_sizes, int n_in,
                              void* d_out, int out_size) {
    const float* feat = (const float*)d_in[0];   // [B,N,F]
    const float* tmpl = (const float*)d_in[1];   // [1,N,N]
    const float* uni  = (const float*)d_in[2];   // [B,N,N]
    float* out = (float*)d_out;                  // [B,N,F]

    cudaFuncSetAttribute(k_gemm, cudaFuncAttributeMaxDynamicSharedMemorySize, NSTAGE * SBUF);

    k_init<<<dim3(NBLK, BB), 512>>>(tmpl, uni);
    k_reduce<<<dim3(32, BB), 256>>>();
    for (int it = 0; it < 8; ++it) {
        k_fused<<<dim3(NBLK, BB), 512>>>();
        k_reduce<<<dim3(32, BB), 256>>>();
    }
    k_fused_last<<<dim3(NBLK, BB), 512>>>();
    k_prepB<<<dim3(NN / 8, BB), 256>>>(feat);
    k_gemm<<<dim3(8, BB), 256, NSTAGE * SBUF>>>(out);
}